// round 2
// baseline (speedup 1.0000x reference)
#include <cuda_runtime.h>

#define N_NODES 100000
#define N_EDGES 1600000
#define DIN 128
#define DHID 256
#define DOUT 64

// Static scratch (no runtime allocation allowed).
__device__ float g_y1[(size_t)N_NODES * DIN];   // layer-1 accumulator: x + A.x
__device__ float g_y2[(size_t)N_NODES * DIN];   // layer-2 accumulator: y1 + A.y1
__device__ float g_wf[DIN * DOUT];              // fused W1 @ W2

// ---------------------------------------------------------------------------
// Wf[i][j] = sum_k W1[i][k] * W2[k][j]   (128 x 256 x 64 — tiny)
// ---------------------------------------------------------------------------
__global__ void fuse_w_kernel(const float* __restrict__ W1,
                              const float* __restrict__ W2) {
    int i = blockIdx.x;
    int j = threadIdx.x;
    float acc = 0.f;
#pragma unroll 8
    for (int k = 0; k < DHID; ++k)
        acc += W1[i * DHID + k] * W2[k * DOUT + j];
    g_wf[i * DOUT + j] = acc;
}

// ---------------------------------------------------------------------------
// Grid-stride float4 copy (accumulator init with the self term; eps=0 means
// (1+eps)*h + agg == h + agg, so starting the scatter target at h is exact).
// ---------------------------------------------------------------------------
__global__ void copy_kernel(const float4* __restrict__ src,
                            float4* __restrict__ dst, int n4) {
    int i = blockIdx.x * blockDim.x + threadIdx.x;
    int stride = gridDim.x * blockDim.x;
    for (; i < n4; i += stride) dst[i] = src[i];
}

// ---------------------------------------------------------------------------
// Warp-per-edge scatter: each lane moves one float4 (128 floats / 32 lanes).
// red.global.add.v4.f32 (sm_90+) -> E*32 LTS atomic ops instead of E*128.
// Edge indices are int32 (JAX x64 disabled downgrades int64 -> int32).
// ---------------------------------------------------------------------------
__global__ void scatter_kernel(const float* __restrict__ feat,
                               float* __restrict__ acc,
                               const int* __restrict__ es,
                               const int* __restrict__ ed) {
    int lane = threadIdx.x & 31;
    int warp = (blockIdx.x * blockDim.x + threadIdx.x) >> 5;
    int nwarp = (gridDim.x * blockDim.x) >> 5;
    for (int e = warp; e < N_EDGES; e += nwarp) {
        int s = __ldg(es + e);
        int d = __ldg(ed + e);
        // Defensive: skip malformed indices instead of faulting.
        if ((unsigned)s >= N_NODES || (unsigned)d >= N_NODES) continue;
        float4 v = *(const float4*)(feat + (size_t)s * DIN + (lane << 2));
        float* p = acc + (size_t)d * DIN + (lane << 2);
        asm volatile("red.global.add.v4.f32 [%0], {%1,%2,%3,%4};"
                     :: "l"(p), "f"(v.x), "f"(v.y), "f"(v.z), "f"(v.w)
                     : "memory");
    }
}

// ---------------------------------------------------------------------------
// out[n][c] = sum_k y[n][k] * Wf[k][c]   ([100k,128] @ [128,64])
// 256 threads, 16 nodes/block; Wf (32KB) staged in smem.
// ---------------------------------------------------------------------------
#define NPB 16
__global__ void gemm_kernel(const float* __restrict__ y, float* __restrict__ out) {
    __shared__ float ws[DIN * DOUT];      // [k][c], 32 KB
    __shared__ float xs[NPB * 129 + 3];
    int tid = threadIdx.x;

    for (int i = tid; i < DIN * DOUT / 4; i += 256)
        ((float4*)ws)[i] = ((const float4*)g_wf)[i];

    int node0 = blockIdx.x * NPB;
    for (int i = tid; i < NPB * DIN / 4; i += 256) {
        int n  = i >> 5;          // 32 float4 per row
        int k4 = i & 31;
        int node = node0 + n;
        float4 v = (node < N_NODES)
                       ? ((const float4*)(y + (size_t)node * DIN))[k4]
                       : make_float4(0.f, 0.f, 0.f, 0.f);
        float* dst = xs + n * 129 + (k4 << 2);
        dst[0] = v.x; dst[1] = v.y; dst[2] = v.z; dst[3] = v.w;
    }
    __syncthreads();

    int n  = tid >> 4;
    int cg = (tid & 15) << 2;
    float a0 = 0.f, a1 = 0.f, a2 = 0.f, a3 = 0.f;
#pragma unroll 8
    for (int k = 0; k < DIN; ++k) {
        float  xv = xs[n * 129 + k];
        float4 w  = *(const float4*)(ws + k * DOUT + cg);
        a0 += xv * w.x; a1 += xv * w.y; a2 += xv * w.z; a3 += xv * w.w;
    }
    int node = node0 + n;
    if (node < N_NODES) {
        float4 r = make_float4(a0, a1, a2, a3);
        *(float4*)(out + (size_t)node * DOUT + cg) = r;
    }
}

// ---------------------------------------------------------------------------
extern "C" void kernel_launch(void* const* d_in, const int* in_sizes, int n_in,
                              void* d_out, int out_size) {
    const float* x  = (const float*)d_in[0];
    const int*   es = (const int*)d_in[1];
    const int*   ed = (const int*)d_in[2];
    const float* W1 = (const float*)d_in[3];
    const float* W2 = (const float*)d_in[4];
    float*       out = (float*)d_out;

    void *p_y1, *p_y2;
    cudaGetSymbolAddress(&p_y1, g_y1);
    cudaGetSymbolAddress(&p_y2, g_y2);
    float* y1 = (float*)p_y1;
    float* y2 = (float*)p_y2;

    const int n4 = N_NODES * DIN / 4;
    const int copy_blocks = 1024;
    const int scat_blocks = 2048;

    fuse_w_kernel<<<DIN, DOUT>>>(W1, W2);

    // Layer 1: y1 = x; y1[dst] += x[src]
    copy_kernel<<<copy_blocks, 256>>>((const float4*)x, (float4*)y1, n4);
    scatter_kernel<<<scat_blocks, 256>>>(x, y1, es, ed);

    // Layer 2 (pre-GEMM aggregation): y2 = y1; y2[dst] += y1[src]
    copy_kernel<<<copy_blocks, 256>>>((const float4*)y1, (float4*)y2, n4);
    scatter_kernel<<<scat_blocks, 256>>>(y1, y2, es, ed);

    // out = y2 @ (W1 @ W2)
    gemm_kernel<<<(N_NODES + NPB - 1) / NPB, 256>>>(y2, out);
}

// round 3
// speedup vs baseline: 1.5492x; 1.5492x over previous
#include <cuda_runtime.h>

#define N_NODES 100000
#define N_EDGES 1600000
#define DIN 128
#define DHID 256
#define DOUT 64

// Static scratch (no runtime allocation allowed).
__device__ float g_z [(size_t)N_NODES * DOUT];  // z  = x @ Wf
__device__ float g_z1[(size_t)N_NODES * DOUT];  // z1 = z + A.z
__device__ float g_wf[DIN * DOUT];              // fused W1 @ W2

// ---------------------------------------------------------------------------
// Wf[i][j] = sum_k W1[i][k] * W2[k][j]   (128 x 256 x 64 — tiny)
// ---------------------------------------------------------------------------
__global__ void fuse_w_kernel(const float* __restrict__ W1,
                              const float* __restrict__ W2) {
    int i = blockIdx.x;
    int j = threadIdx.x;
    float acc = 0.f;
#pragma unroll 8
    for (int k = 0; k < DHID; ++k)
        acc += W1[i * DHID + k] * W2[k * DOUT + j];
    g_wf[i * DOUT + j] = acc;
}

// ---------------------------------------------------------------------------
// z[n][c] = sum_k x[n][k] * Wf[k][c]   ([100k,128] @ [128,64])
// Dual epilogue: writes z AND seeds the layer-1 accumulator z1 with the same
// value (self term; eps=0), eliminating a separate 25.6MB copy pass.
// ---------------------------------------------------------------------------
#define NPB 16
__global__ void gemm_kernel(const float* __restrict__ x,
                            float* __restrict__ z,
                            float* __restrict__ z1) {
    __shared__ float ws[DIN * DOUT];      // [k][c], 32 KB
    __shared__ float xs[NPB * 129 + 3];
    int tid = threadIdx.x;

    for (int i = tid; i < DIN * DOUT / 4; i += 256)
        ((float4*)ws)[i] = ((const float4*)g_wf)[i];

    int node0 = blockIdx.x * NPB;
    for (int i = tid; i < NPB * DIN / 4; i += 256) {
        int n  = i >> 5;          // 32 float4 per row
        int k4 = i & 31;
        int node = node0 + n;
        float4 v = (node < N_NODES)
                       ? ((const float4*)(x + (size_t)node * DIN))[k4]
                       : make_float4(0.f, 0.f, 0.f, 0.f);
        float* dst = xs + n * 129 + (k4 << 2);
        dst[0] = v.x; dst[1] = v.y; dst[2] = v.z; dst[3] = v.w;
    }
    __syncthreads();

    int n  = tid >> 4;
    int cg = (tid & 15) << 2;
    float a0 = 0.f, a1 = 0.f, a2 = 0.f, a3 = 0.f;
#pragma unroll 8
    for (int k = 0; k < DIN; ++k) {
        float  xv = xs[n * 129 + k];
        float4 w  = *(const float4*)(ws + k * DOUT + cg);
        a0 += xv * w.x; a1 += xv * w.y; a2 += xv * w.z; a3 += xv * w.w;
    }
    int node = node0 + n;
    if (node < N_NODES) {
        float4 r = make_float4(a0, a1, a2, a3);
        *(float4*)(z  + (size_t)node * DOUT + cg) = r;
        *(float4*)(z1 + (size_t)node * DOUT + cg) = r;
    }
}

// ---------------------------------------------------------------------------
// Grid-stride float4 copy (seed the final accumulator = d_out with z1).
// ---------------------------------------------------------------------------
__global__ void copy_kernel(const float4* __restrict__ src,
                            float4* __restrict__ dst, int n4) {
    int i = blockIdx.x * blockDim.x + threadIdx.x;
    int stride = gridDim.x * blockDim.x;
    for (; i < n4; i += stride) dst[i] = src[i];
}

// ---------------------------------------------------------------------------
// Half-warp-per-edge scatter in the 64-dim: 16 lanes x float4 = one row.
// red.global.add.v4.f32 -> 16 LTS atomic ops per edge. Indices are int32
// (JAX x64 disabled downgrades the reference's int64 to int32).
// ---------------------------------------------------------------------------
__global__ void scatter64_kernel(const float* __restrict__ feat,
                                 float* __restrict__ acc,
                                 const int* __restrict__ es,
                                 const int* __restrict__ ed) {
    int t = blockIdx.x * blockDim.x + threadIdx.x;
    int slot = t >> 4;                     // one edge per 16 threads
    int l16  = t & 15;                     // float4 index within the row
    int nslot = (gridDim.x * blockDim.x) >> 4;
    for (int e = slot; e < N_EDGES; e += nslot) {
        int s = __ldg(es + e);
        int d = __ldg(ed + e);
        if ((unsigned)s >= N_NODES || (unsigned)d >= N_NODES) continue;
        float4 v = *(const float4*)(feat + (size_t)s * DOUT + (l16 << 2));
        float* p = acc + (size_t)d * DOUT + (l16 << 2);
        asm volatile("red.global.add.v4.f32 [%0], {%1,%2,%3,%4};"
                     :: "l"(p), "f"(v.x), "f"(v.y), "f"(v.z), "f"(v.w)
                     : "memory");
    }
}

// ---------------------------------------------------------------------------
extern "C" void kernel_launch(void* const* d_in, const int* in_sizes, int n_in,
                              void* d_out, int out_size) {
    const float* x  = (const float*)d_in[0];
    const int*   es = (const int*)d_in[1];
    const int*   ed = (const int*)d_in[2];
    const float* W1 = (const float*)d_in[3];
    const float* W2 = (const float*)d_in[4];
    float*       out = (float*)d_out;

    void *p_z, *p_z1;
    cudaGetSymbolAddress(&p_z,  g_z);
    cudaGetSymbolAddress(&p_z1, g_z1);
    float* z  = (float*)p_z;
    float* z1 = (float*)p_z1;

    const int n4 = N_NODES * DOUT / 4;     // 1.6M float4
    const int copy_blocks = 1024;
    const int scat_blocks = 2048;

    // out = (I+A)^2 x Wf  — project first, aggregate twice in the 64-dim.
    fuse_w_kernel<<<DIN, DOUT>>>(W1, W2);
    gemm_kernel<<<(N_NODES + NPB - 1) / NPB, 256>>>(x, z, z1);

    // z1 = z + A.z
    scatter64_kernel<<<scat_blocks, 256>>>(z, z1, es, ed);

    // out = z1 + A.z1
    copy_kernel<<<copy_blocks, 256>>>((const float4*)z1, (float4*)out, n4);
    scatter64_kernel<<<scat_blocks, 256>>>(z1, out, es, ed);
}